// round 16
// baseline (speedup 1.0000x reference)
#include <cuda_runtime.h>
#include <cuda_bf16.h>
#include <math.h>

// Problem constants
#define PP      2048
#define BB      512
#define MCMULT  (4.0f / 2048.0f)
#define EPSV    1e-9f

// Launch geometry: thread = one point; block = 256 points x NB batches
#define PTB     256
#define NB      4
#define GX      (PP / PTB)             // 8
#define GY      (BB / NB)              // 128
#define NBLK    (GX * GY)              // 1024 blocks -> ~7 blocks/SM demand

__device__ double g_partials[NBLK];
__device__ unsigned int g_cnt;         // zero-init; reset by last block each replay

static __device__ __forceinline__ __nv_bfloat162 bcast2(const unsigned int& u) {
    return *reinterpret_cast<const __nv_bfloat162*>(&u);
}

__global__ __launch_bounds__(256, 5)
void mb_bf16v2_kernel(const float* __restrict__ cw,
                      const float* __restrict__ pts,
                      const int*   __restrict__ nf1,
                      float*       __restrict__ out)
{
    // Box rows: [mn0..mn15 | mx0..mx15] bf16x2 = 128B per (class,k) box row.
    // 4*NB = 16 rows. Mainloop reads are warp-uniform -> LDS broadcasts.
    __shared__ unsigned int s_box[4 * NB][32];
    __shared__ int    s_idx[2 * NB];
    __shared__ double s_wsum[8];
    __shared__ int    s_flag;

    const int tid   = threadIdx.x;
    const int w     = tid >> 5;
    const int lane  = tid & 31;
    const int pbase = blockIdx.x * PTB;
    const int b0    = blockIdx.y * NB;

    if (tid < 2 * NB) s_idx[tid] = nf1[b0 * 2 + tid];
    __syncthreads();

    // ── Stage boxes: threads 0..127 -> (box_row r in [0,16), dim-group g in [0,8))
    if (tid < 4 * NB * 8) {
        int r = tid >> 3, g = tid & 7;
        int cls = s_idx[r >> 1];
        int k   = r & 1;
        const float4* base = (const float4*)(cw + (size_t)cls * 128 + (size_t)k * 64);
        float4 c4 = base[g];        // c dims g*4..g*4+3
        float4 o4 = base[8 + g];    // o dims g*4..g*4+3
        float ax = fabsf(o4.x), ay = fabsf(o4.y), az = fabsf(o4.z), aw = fabsf(o4.w);
        __nv_bfloat162 mn0 = __floats2bfloat162_rn(c4.x - ax, c4.y - ay);
        __nv_bfloat162 mn1 = __floats2bfloat162_rn(c4.z - az, c4.w - aw);
        __nv_bfloat162 mx0 = __floats2bfloat162_rn(c4.x + ax, c4.y + ay);
        __nv_bfloat162 mx1 = __floats2bfloat162_rn(c4.z + az, c4.w + aw);
        s_box[r][g * 2 + 0]      = *reinterpret_cast<unsigned int*>(&mn0);
        s_box[r][g * 2 + 1]      = *reinterpret_cast<unsigned int*>(&mn1);
        s_box[r][16 + g * 2 + 0] = *reinterpret_cast<unsigned int*>(&mx0);
        s_box[r][16 + g * 2 + 1] = *reinterpret_cast<unsigned int*>(&mx1);
    }

    // ── This thread's point: straight from gmem (L2-resident), cvt to bf16x2
    __nv_bfloat162 p2[16];
    {
        const float4* pr = (const float4*)(pts + (size_t)(pbase + tid) * 32);
#pragma unroll
        for (int j = 0; j < 8; j++) {
            float4 v = pr[j];
            p2[j * 2 + 0] = __floats2bfloat162_rn(v.x, v.y);
            p2[j * 2 + 1] = __floats2bfloat162_rn(v.z, v.w);
        }
    }
    __syncthreads();

    const __nv_bfloat162 binf = __float2bfloat162_rn(3.0e38f);

    float lsum = 0.0f;
#pragma unroll 1
    for (int b = 0; b < NB; b++) {
        float m[4];
#pragma unroll
        for (int box = 0; box < 4; box++) {
            int r = (2 * b + (box >> 1)) * 2 + (box & 1);
            const unsigned int* BR = s_box[r];
            __nv_bfloat162 a0 = binf, a1 = binf, a2 = binf, a3 = binf;
#pragma unroll
            for (int j = 0; j < 4; j++) {
                uint4 mn4 = *(const uint4*)(BR + j * 4);        // broadcast
                uint4 mx4 = *(const uint4*)(BR + 16 + j * 4);   // broadcast
                int q = j * 4;
                // margin2 = min(p - mn, mx - p), 2 dims per op
                a0 = __hmin2(a0, __hmin2(__hsub2(p2[q + 0], bcast2(mn4.x)),
                                         __hsub2(bcast2(mx4.x), p2[q + 0])));
                a1 = __hmin2(a1, __hmin2(__hsub2(p2[q + 1], bcast2(mn4.y)),
                                         __hsub2(bcast2(mx4.y), p2[q + 1])));
                a2 = __hmin2(a2, __hmin2(__hsub2(p2[q + 2], bcast2(mn4.z)),
                                         __hsub2(bcast2(mx4.z), p2[q + 2])));
                a3 = __hmin2(a3, __hmin2(__hsub2(p2[q + 3], bcast2(mn4.w)),
                                         __hsub2(bcast2(mx4.w), p2[q + 3])));
            }
            a0 = __hmin2(a0, a1);
            a2 = __hmin2(a2, a3);
            a0 = __hmin2(a0, a2);
            m[box] = fminf(__low2float(a0), __high2float(a0));
        }
        float mc = fmaxf(m[0], m[1]);           // sigmoid(max)==max(sigmoid)
        float md = fmaxf(m[2], m[3]);
        float ci = 1.0f / (1.0f + __expf(-mc));
        float di = 1.0f / (1.0f + __expf(-md));
        float inter = (ci + di) * 0.5f;
        float area1 = fmaxf(ci - 0.5f, 0.0f) * MCMULT;
        float iarea = fmaxf(inter - 0.5f, 0.0f) * MCMULT;
        lsum += __fdividef(iarea, area1 + EPSV);
    }

    // Reduce: warp (double) -> block -> grid via last-block-done
    double v = (double)lsum;
#pragma unroll
    for (int s = 16; s > 0; s >>= 1)
        v += __shfl_down_sync(0xFFFFFFFFu, v, s);
    if (lane == 0) s_wsum[w] = v;
    __syncthreads();

    if (w == 0) {
        double t = (lane < 8) ? s_wsum[lane] : 0.0;
#pragma unroll
        for (int s = 4; s > 0; s >>= 1)
            t += __shfl_down_sync(0xFFFFFFFFu, t, s);
        if (lane == 0) {
            int bid = blockIdx.y * gridDim.x + blockIdx.x;
            g_partials[bid] = t;
            __threadfence();
            unsigned old = atomicAdd(&g_cnt, 1u);
            s_flag = (old == NBLK - 1) ? 1 : 0;
        }
    }
    __syncthreads();

    if (s_flag) {   // last block: reduce all 1024 partials (4 per thread)
        double s = g_partials[tid] + g_partials[tid + 256]
                 + g_partials[tid + 512] + g_partials[tid + 768];
#pragma unroll
        for (int k = 16; k > 0; k >>= 1)
            s += __shfl_down_sync(0xFFFFFFFFu, s, k);
        if (lane == 0) s_wsum[w] = s;
        __syncthreads();
        if (w == 0) {
            double t = (lane < 8) ? s_wsum[lane] : 0.0;
#pragma unroll
            for (int k = 4; k > 0; k >>= 1)
                t += __shfl_down_sync(0xFFFFFFFFu, t, k);
            if (lane == 0) {
                double loss = 1.0 - t / ((double)BB * (double)PP);
                out[0] = (float)(loss > 0.0 ? loss : 0.0);
                g_cnt = 0u;                     // reset for next graph replay
            }
        }
    }
}

extern "C" void kernel_launch(void* const* d_in, const int* in_sizes, int n_in,
                              void* d_out, int out_size)
{
    const float* cw  = (const float*)d_in[0];   // class_weight (50000,128)
    const float* pts = (const float*)d_in[1];   // mc_points    (2048,32)
    const int*   nf1 = (const int*)  d_in[2];   // nf1_data     (512,2)

    dim3 grid(GX, GY);
    mb_bf16v2_kernel<<<grid, PTB>>>(cw, pts, nf1, (float*)d_out);
}